// round 2
// baseline (speedup 1.0000x reference)
#include <cuda_runtime.h>
#include <cstdint>

#define Bsz   128
#define TIN   240
#define TOUT  30
#define Dd    128
#define Hh    256
#define G3    768
#define ENC_L (TIN*Bsz)   /* 30720 */
#define DEC_L (TOUT*Bsz)  /* 3840  */

// scratch: precomputed gi = x_seq @ Wih^T + (bih + bhh[r,z gates])
__device__ float g_gi_enc[(size_t)ENC_L * G3];   // ~94 MB
__device__ float g_gi_dec[(size_t)DEC_L * G3];   // ~12 MB

typedef unsigned long long u64t;

__device__ __forceinline__ u64t ffma2(u64t a, u64t b, u64t c) {
    u64t d;
    asm("fma.rn.f32x2 %0, %1, %2, %3;" : "=l"(d) : "l"(a), "l"(b), "l"(c));
    return d;
}
__device__ __forceinline__ u64t fadd2(u64t a, u64t b) {
    u64t d;
    asm("add.rn.f32x2 %0, %1, %2;" : "=l"(d) : "l"(a), "l"(b));
    return d;
}
__device__ __forceinline__ float sumpair(u64t a) {
    float x, y;
    asm("mov.b64 {%0, %1}, %2;" : "=f"(x), "=f"(y) : "l"(a));
    return x + y;
}

// ===================== Kernel 1: gi GEMM =====================
// Gi[s, c] = sum_d X[b, t, d] * Wih[c, d] + bih[c] + (c<512 ? bhh[c] : 0)
//   s = t*128 + b ; t = (s>>7)*tstride
__global__ void __launch_bounds__(256) gi_gemm(
    const float* __restrict__ X, const float* __restrict__ Wih,
    const float* __restrict__ bih, const float* __restrict__ bhh,
    int tstride, int which)
{
    float* __restrict__ Gi = which ? g_gi_dec : g_gi_enc;
    __shared__ float As[64][65];
    __shared__ float Bs[64][65];
    const int tid = threadIdx.x;
    const int tx = tid & 15, ty = tid >> 4;
    const int row0 = blockIdx.y * 64, col0 = blockIdx.x * 64;
    float acc[4][4];
#pragma unroll
    for (int p = 0; p < 4; p++)
#pragma unroll
        for (int q = 0; q < 4; q++) acc[p][q] = 0.f;

    for (int kk = 0; kk < 128; kk += 64) {
#pragma unroll
        for (int i = 0; i < 16; i++) {
            int e = i * 256 + tid;
            int r = e >> 6, k = e & 63;
            int s = row0 + r;
            int b = s & 127, t = (s >> 7) * tstride;
            As[r][k] = X[((size_t)b * TIN + t) * 128 + kk + k];
        }
#pragma unroll
        for (int i = 0; i < 16; i++) {
            int e = i * 256 + tid;
            int c = e >> 6, k = e & 63;
            Bs[k][c] = Wih[(size_t)(col0 + c) * 128 + kk + k];
        }
        __syncthreads();
#pragma unroll 8
        for (int k = 0; k < 64; k++) {
            float a[4], b[4];
#pragma unroll
            for (int q = 0; q < 4; q++) a[q] = As[ty * 4 + q][k];
#pragma unroll
            for (int q = 0; q < 4; q++) b[q] = Bs[k][tx * 4 + q];
#pragma unroll
            for (int p = 0; p < 4; p++)
#pragma unroll
                for (int q = 0; q < 4; q++) acc[p][q] = fmaf(a[p], b[q], acc[p][q]);
        }
        __syncthreads();
    }
#pragma unroll
    for (int p = 0; p < 4; p++) {
        int s = row0 + ty * 4 + p;
#pragma unroll
        for (int q = 0; q < 4; q++) {
            int c = col0 + tx * 4 + q;
            float bias = bih[c] + (c < 512 ? bhh[c] : 0.f);
            Gi[(size_t)s * G3 + c] = acc[p][q] + bias;
        }
    }
}

// ===================== Kernel 2: sequential GRU scan =====================
// grid = 16 CTAs = 2 clusters of 8 (cluster 0: encoder, cluster 1: decoder).
// Each CTA owns 96 of the 768 gh-rows (32 per gate), weights in registers.
// Per step: reg-weight matvec (f32x2 FMA) + shfl reduce -> warp 0 computes 32
// h_new, broadcasts to all 8 CTAs via DSMEM, one cluster barrier per step.
__global__ void __launch_bounds__(768, 1) __cluster_dims__(8, 1, 1)
gru_scan(const float* __restrict__ Whh_e, const float* __restrict__ bhh_e,
         const float* __restrict__ Whh_d, const float* __restrict__ bhh_d,
         float* __restrict__ out)
{
    __shared__ float hbuf[2][Hh];   // double-buffered h
    __shared__ float stage[96];     // per-CTA gh rows

    const int which = blockIdx.x >> 3;      // 0 = encoder, 1 = decoder
    const int crank = blockIdx.x & 7;       // rank within cluster
    const float* __restrict__ Whh = which ? Whh_d : Whh_e;
    const float* __restrict__ bhh = which ? bhh_d : bhh_e;
    const float* __restrict__ gi  = which ? g_gi_dec : g_gi_enc;
    float* __restrict__ out_enc = out;                 // (240, 256)
    float* __restrict__ out_dec = out + (size_t)TIN * Hh; // (128, 30, 256)
    const int L = which ? DEC_L : ENC_L;

    const int tid = threadIdx.x;
    const int w = tid >> 5, lane = tid & 31;
    const int kc = lane >> 2;        // k-chunk 0..7 (32 floats each)
    const int rl = lane & 3;         // row-in-warp 0..3
    const int l  = 4 * w + rl;       // local row 0..95
    const int g  = l >> 5, j = l & 31;
    const int R  = g * 256 + crank * 32 + j;   // global gh row

    // weight slice into registers: Whh[R, kc*32 .. kc*32+32)
    u64t wreg[16];
    {
        const ulonglong2* wp =
            (const ulonglong2*)(Whh + (size_t)R * Hh + kc * 32);
#pragma unroll
        for (int i = 0; i < 8; i++) {
            ulonglong2 v = wp[i];
            wreg[2 * i]     = v.x;
            wreg[2 * i + 1] = v.y;
        }
    }
    // bhh for the n-gate rows only (r/z bhh folded into gi)
    const float hb = (g == 2) ? bhh[512 + crank * 32 + j] : 0.f;

    if (tid < Hh) { hbuf[0][tid] = 0.f; hbuf[1][tid] = 0.f; }

    // warp 0: gi prefetch pointers + step-0 preload
    const float* gp = gi + crank * 32 + lane;
    float ga = 0.f, gb = 0.f, gc = 0.f;
    if (w == 0) { ga = __ldg(gp); gb = __ldg(gp + 256); gc = __ldg(gp + 512); }
    __syncthreads();

    for (int s = 0; s < L; s++) {
        const int cur = s & 1, nxt = cur ^ 1;

        // prefetch gi for step s+1 (independent of h)
        float na = 0.f, nb = 0.f, nc = 0.f;
        if (w == 0 && s + 1 < L) {
            const float* q = gp + (size_t)(s + 1) * G3;
            na = __ldg(q); nb = __ldg(q + 256); nc = __ldg(q + 512);
        }

        // cluster barrier: h[cur] from all 8 CTAs visible
        asm volatile("barrier.cluster.arrive.aligned;" ::: "memory");
        asm volatile("barrier.cluster.wait.aligned;" ::: "memory");

        // matvec partial: dot(Whh[R, kc*32..+32), h[kc*32..+32))
        const ulonglong2* hp = (const ulonglong2*)&hbuf[cur][kc * 32];
        u64t a0 = 0ull, a1 = 0ull, a2 = 0ull, a3 = 0ull;
#pragma unroll
        for (int i = 0; i < 4; i++) {
            ulonglong2 h0 = hp[2 * i];
            ulonglong2 h1 = hp[2 * i + 1];
            a0 = ffma2(wreg[4 * i + 0], h0.x, a0);
            a1 = ffma2(wreg[4 * i + 1], h0.y, a1);
            a2 = ffma2(wreg[4 * i + 2], h1.x, a2);
            a3 = ffma2(wreg[4 * i + 3], h1.y, a3);
        }
        float v = sumpair(fadd2(fadd2(a0, a1), fadd2(a2, a3)));
        // reduce across the 8 lanes (same rl) of this warp
        v += __shfl_xor_sync(0xffffffffu, v, 4);
        v += __shfl_xor_sync(0xffffffffu, v, 8);
        v += __shfl_xor_sync(0xffffffffu, v, 16);
        if (kc == 0) stage[l] = v + hb;
        __syncthreads();

        if (w == 0) {
            const float gr = ga + stage[lane];
            const float gz = gb + stage[32 + lane];
            const float hn = stage[64 + lane];
            const float r = 1.f / (1.f + __expf(-gr));
            const float z = 1.f / (1.f + __expf(-gz));
            float n = gc + r * hn;
            n = 2.f / (1.f + __expf(-2.f * n)) - 1.f;   // tanh, inf-safe
            const float hprev = hbuf[cur][crank * 32 + lane];
            const float hnew  = n + z * (hprev - n);

            // broadcast my 32-chunk of h_new to all 8 CTAs (buffer nxt)
            uint32_t laddr = (uint32_t)__cvta_generic_to_shared(
                &hbuf[nxt][crank * 32 + lane]);
#pragma unroll
            for (int t = 0; t < 8; t++) {
                uint32_t ra;
                asm("mapa.shared::cluster.u32 %0, %1, %2;"
                    : "=r"(ra) : "r"(laddr), "r"(t));
                asm volatile("st.shared::cluster.f32 [%0], %1;"
                             :: "r"(ra), "f"(hnew) : "memory");
            }

            if (which) {
                const int b = s & 127, t = s >> 7;
                out_dec[((size_t)b * TOUT + t) * Hh + crank * 32 + lane] = hnew;
            } else if ((s & 127) == 127) {
                const int t = s >> 7;
                out_enc[(size_t)t * Hh + crank * 32 + lane] = hnew;
            }
            ga = na; gb = nb; gc = nc;
        }
    }

    // final cluster barrier: don't exit while peers' DSMEM stores in flight
    asm volatile("barrier.cluster.arrive.aligned;" ::: "memory");
    asm volatile("barrier.cluster.wait.aligned;" ::: "memory");
}

extern "C" void kernel_launch(void* const* d_in, const int* in_sizes, int n_in,
                              void* d_out, int out_size) {
    const float* x        = (const float*)d_in[0];
    const float* W_ih_enc = (const float*)d_in[1];
    const float* W_hh_enc = (const float*)d_in[2];
    const float* b_ih_enc = (const float*)d_in[3];
    const float* b_hh_enc = (const float*)d_in[4];
    const float* W_ih_dec = (const float*)d_in[5];
    const float* W_hh_dec = (const float*)d_in[6];
    const float* b_ih_dec = (const float*)d_in[7];
    const float* b_hh_dec = (const float*)d_in[8];
    float* out = (float*)d_out;

    // 1) precompute input gates (encoder: stride 1, decoder: stride 8)
    gi_gemm<<<dim3(G3 / 64, ENC_L / 64), 256>>>(
        x, W_ih_enc, b_ih_enc, b_hh_enc, 1, 0);
    gi_gemm<<<dim3(G3 / 64, DEC_L / 64), 256>>>(
        x, W_ih_dec, b_ih_dec, b_hh_dec, 8, 1);

    // 2) sequential scans: 2 clusters of 8 CTAs (encoder + decoder concurrent)
    gru_scan<<<16, 768>>>(W_hh_enc, b_hh_enc, W_hh_dec, b_hh_dec, out);
}